// round 1
// baseline (speedup 1.0000x reference)
#include <cuda_runtime.h>
#include <math.h>

#define NN   200000
#define HH   128
#define OUTD 256
#define BMAXG 1024
#define BM   128

// ---------------- scratch (device globals; no allocation) ----------------
__device__ float g_bufA[(size_t)NN * HH];   // 102.4 MB
__device__ float g_bufB[(size_t)NN * HH];   // 102.4 MB
__device__ float g_agg [(size_t)NN * HH];   // 102.4 MB
__device__ int   g_deg [NN];
__device__ float g_invn[NN];
__device__ float g_gsum[BMAXG * HH];
__device__ int   g_cnt [BMAXG];

// ---------------- helpers ----------------
__device__ __forceinline__ void redAdd4(float* p, float4 v) {
    asm volatile("red.global.add.v4.f32 [%0], {%1,%2,%3,%4};"
                 :: "l"(p), "f"(v.x), "f"(v.y), "f"(v.z), "f"(v.w) : "memory");
}

__device__ __forceinline__ float gelu_exact(float v) {
    return 0.5f * v * (1.0f + erff(v * 0.70710678118654752f));
}

// ---------------- zero kernels ----------------
__global__ void zero_f_k(float* p, int n4) {   // n4 = count of float4
    int i = blockIdx.x * blockDim.x + threadIdx.x;
    int s = gridDim.x * blockDim.x;
    float4 z = make_float4(0.f, 0.f, 0.f, 0.f);
    for (int f = i; f < n4; f += s) ((float4*)p)[f] = z;
}
__global__ void zero_i_k(int* p, int n) {
    int i = blockIdx.x * blockDim.x + threadIdx.x;
    int s = gridDim.x * blockDim.x;
    for (int f = i; f < n; f += s) p[f] = 0;
}

// ---------------- degree ----------------
__global__ void deg_k(const int* __restrict__ src, const int* __restrict__ dst,
                      int* __restrict__ deg, int E) {
    int e = blockIdx.x * blockDim.x + threadIdx.x;
    if (e < E) {
        atomicAdd(&deg[src[e]], 1);
        atomicAdd(&deg[dst[e]], 1);
    }
}

// ---------------- embedding gather + invnorm ----------------
__global__ void gather_k(const int* __restrict__ x, const float* __restrict__ emb,
                         const int* __restrict__ deg, float* __restrict__ h,
                         float* __restrict__ invn, int n) {
    int gt = blockIdx.x * blockDim.x + threadIdx.x;
    int nd = gt >> 5, k4 = gt & 31;
    if (nd >= n) return;
    int t = x[nd];
    ((float4*)(h + (size_t)nd * HH))[k4] = ((const float4*)(emb + (size_t)t * HH))[k4];
    if (k4 == 0) invn[nd] = rsqrtf(fmaxf((float)deg[nd], 1.0f));
}

// ---------------- edge scatter (both directions per undirected edge) ----------------
__global__ void scatter_k(const float* __restrict__ h, const int* __restrict__ src,
                          const int* __restrict__ dst, float* __restrict__ agg, int E) {
    int lane = threadIdx.x & 31;
    int warp = (blockIdx.x * blockDim.x + threadIdx.x) >> 5;
    int nw   = (gridDim.x * blockDim.x) >> 5;
    for (int e = warp; e < E; e += nw) {
        int s = src[e], d = dst[e];
        float4 hs = __ldg(((const float4*)(h + (size_t)s * HH)) + lane);
        float4 hd = __ldg(((const float4*)(h + (size_t)d * HH)) + lane);
        redAdd4(agg + (size_t)d * HH + lane * 4, hs);
        redAdd4(agg + (size_t)s * HH + lane * 4, hd);
    }
}

// ---------------- combine: out = gelu((agg*invn) @ W + b + hprev) ----------------
// 128x128 tile, 256 threads, 8x8 microtile, K=128 fully resident in smem.
__global__ void combine_k(const float* __restrict__ agg, const float* __restrict__ hprev,
                          const float* __restrict__ W, const float* __restrict__ bias,
                          const float* __restrict__ invn, float* __restrict__ hout, int n) {
    extern __shared__ float smem[];
    float* As = smem;              // [128][128] node rows (already deg-normalized)
    float* Ws = smem + BM * HH;    // [128][128] weight rows
    int tid = threadIdx.x;
    int m0  = blockIdx.x * BM;

    // load W (row-major copy)
    for (int f = tid; f < HH * HH / 4; f += 256)
        ((float4*)Ws)[f] = ((const float4*)W)[f];

    // load A tile with invnorm scaling
    for (int f = tid; f < BM * 32; f += 256) {
        int m = f >> 5, k4 = f & 31;
        int gm = m0 + m;
        float4 v = make_float4(0.f, 0.f, 0.f, 0.f);
        if (gm < n) {
            v = ((const float4*)(agg + (size_t)gm * HH))[k4];
            float sc = invn[gm];
            v.x *= sc; v.y *= sc; v.z *= sc; v.w *= sc;
        }
        ((float4*)(As + m * HH))[k4] = v;
    }
    __syncthreads();

    int tm = (tid >> 4) << 3;      // row base in tile (0..120)
    int tn = (tid & 15) << 3;      // col base (0..120)

    float acc[8][8];
#pragma unroll
    for (int i = 0; i < 8; i++)
#pragma unroll
        for (int j = 0; j < 8; j++) acc[i][j] = 0.f;

#pragma unroll 1
    for (int kb = 0; kb < HH; kb += 4) {
        float4 a4[8];
#pragma unroll
        for (int i = 0; i < 8; i++)
            a4[i] = *(const float4*)(As + (tm + i) * HH + kb);
#pragma unroll
        for (int kk = 0; kk < 4; kk++) {
            float4 w0 = *(const float4*)(Ws + (kb + kk) * HH + tn);
            float4 w1 = *(const float4*)(Ws + (kb + kk) * HH + tn + 4);
#pragma unroll
            for (int i = 0; i < 8; i++) {
                float a = ((const float*)&a4[i])[kk];
                acc[i][0] = fmaf(a, w0.x, acc[i][0]);
                acc[i][1] = fmaf(a, w0.y, acc[i][1]);
                acc[i][2] = fmaf(a, w0.z, acc[i][2]);
                acc[i][3] = fmaf(a, w0.w, acc[i][3]);
                acc[i][4] = fmaf(a, w1.x, acc[i][4]);
                acc[i][5] = fmaf(a, w1.y, acc[i][5]);
                acc[i][6] = fmaf(a, w1.z, acc[i][6]);
                acc[i][7] = fmaf(a, w1.w, acc[i][7]);
            }
        }
    }

    // epilogue: bias + residual + exact GELU
    float4 b0v = ((const float4*)bias)[tn >> 2];
    float4 b1v = ((const float4*)bias)[(tn >> 2) + 1];
#pragma unroll 1
    for (int i = 0; i < 8; i++) {
        int gm = m0 + tm + i;
        if (gm >= n) break;
        const float4* hp = (const float4*)(hprev + (size_t)gm * HH);
        float4 h0 = hp[tn >> 2];
        float4 h1 = hp[(tn >> 2) + 1];
        float4 o0, o1;
        o0.x = gelu_exact(acc[i][0] + b0v.x + h0.x);
        o0.y = gelu_exact(acc[i][1] + b0v.y + h0.y);
        o0.z = gelu_exact(acc[i][2] + b0v.z + h0.z);
        o0.w = gelu_exact(acc[i][3] + b0v.w + h0.w);
        o1.x = gelu_exact(acc[i][4] + b1v.x + h1.x);
        o1.y = gelu_exact(acc[i][5] + b1v.y + h1.y);
        o1.z = gelu_exact(acc[i][6] + b1v.z + h1.z);
        o1.w = gelu_exact(acc[i][7] + b1v.w + h1.w);
        float4* op = (float4*)(hout + (size_t)gm * HH);
        op[tn >> 2]       = o0;
        op[(tn >> 2) + 1] = o1;
    }
}

// ---------------- pooling (segment sum via vector reds) ----------------
__global__ void pool_k(const float* __restrict__ h, const int* __restrict__ batch,
                       float* __restrict__ gsum, int* __restrict__ cnt, int n) {
    int gt = blockIdx.x * blockDim.x + threadIdx.x;
    int nd = gt >> 5, lane = gt & 31;
    if (nd >= n) return;
    int b = batch[nd];
    float4 v = ((const float4*)(h + (size_t)nd * HH))[lane];
    redAdd4(gsum + (size_t)b * HH + lane * 4, v);
    if (lane == 0) atomicAdd(&cnt[b], 1);
}

// ---------------- final: gfeat @ Wo + bo, layernorm ----------------
__global__ void final_k(const float* __restrict__ gsum, const int* __restrict__ cnt,
                        const float* __restrict__ Wo, const float* __restrict__ bo,
                        const float* __restrict__ gamma, const float* __restrict__ beta,
                        float* __restrict__ out) {
    __shared__ float g[HH];
    __shared__ float rs[8], rq[8];
    int b = blockIdx.x, tid = threadIdx.x;
    if (tid < HH) g[tid] = gsum[(size_t)b * HH + tid] / fmaxf((float)cnt[b], 1.0f);
    __syncthreads();
    float acc = bo[tid];
#pragma unroll 4
    for (int k = 0; k < HH; k++) acc = fmaf(g[k], Wo[k * OUTD + tid], acc);
    float s = acc, q = acc * acc;
#pragma unroll
    for (int o = 16; o; o >>= 1) {
        s += __shfl_xor_sync(0xFFFFFFFFu, s, o);
        q += __shfl_xor_sync(0xFFFFFFFFu, q, o);
    }
    int w = tid >> 5;
    if ((tid & 31) == 0) { rs[w] = s; rq[w] = q; }
    __syncthreads();
    float ts = 0.f, tq = 0.f;
#pragma unroll
    for (int i = 0; i < 8; i++) { ts += rs[i]; tq += rq[i]; }
    float mu  = ts * (1.0f / OUTD);
    float var = tq * (1.0f / OUTD) - mu * mu;
    out[(size_t)b * OUTD + tid] = (acc - mu) * rsqrtf(var + 1e-5f) * gamma[tid] + beta[tid];
}

// ---------------- launch ----------------
extern "C" void kernel_launch(void* const* d_in, const int* in_sizes, int n_in,
                              void* d_out, int out_size) {
    const int* x     = (const int*)d_in[0];
    const int* ei    = (const int*)d_in[1];
    const int* batch = (const int*)d_in[2];
    // batch_size may arrive as a size-1 input at slot 3; detect and skip.
    int off = (n_in >= 13 && in_sizes[3] == 1) ? 4 : 3;
    const float* emb   = (const float*)d_in[off + 0];
    const float* W0    = (const float*)d_in[off + 1];
    const float* b0    = (const float*)d_in[off + 2];
    const float* W1    = (const float*)d_in[off + 3];
    const float* b1    = (const float*)d_in[off + 4];
    const float* Wo    = (const float*)d_in[off + 5];
    const float* bo    = (const float*)d_in[off + 6];
    const float* gamma = (const float*)d_in[off + 7];
    const float* beta  = (const float*)d_in[off + 8];

    int N = in_sizes[0];
    int E = in_sizes[1] / 2;
    int B = out_size / OUTD;

    float *bufA, *bufB, *agg, *invn, *gsum;
    int *deg, *cnt;
    cudaGetSymbolAddress((void**)&bufA, g_bufA);
    cudaGetSymbolAddress((void**)&bufB, g_bufB);
    cudaGetSymbolAddress((void**)&agg,  g_agg);
    cudaGetSymbolAddress((void**)&invn, g_invn);
    cudaGetSymbolAddress((void**)&gsum, g_gsum);
    cudaGetSymbolAddress((void**)&deg,  g_deg);
    cudaGetSymbolAddress((void**)&cnt,  g_cnt);

    cudaFuncSetAttribute(combine_k, cudaFuncAttributeMaxDynamicSharedMemorySize, 131072);

    const int* src = ei;
    const int* dst = ei + E;

    int gthr = N * 32;               // one thread per float4 of h
    int gblk = (gthr + 255) / 256;
    int cblk = (N + BM - 1) / BM;

    // zero scratch
    zero_f_k<<<4096, 256>>>(agg, N * HH / 4);
    zero_i_k<<<256, 256>>>(deg, N);
    zero_f_k<<<64, 256>>>(gsum, B * HH / 4);
    zero_i_k<<<1, 256>>>(cnt, B);

    // degree + embedding gather + invnorm
    deg_k<<<(E + 255) / 256, 256>>>(src, dst, deg, E);
    gather_k<<<gblk, 256>>>(x, emb, deg, bufA, invn, N);

    // layer 1
    scatter_k<<<2048, 256>>>(bufA, src, dst, agg, E);
    combine_k<<<cblk, 256, 131072>>>(agg, bufA, W0, b0, invn, bufB, N);

    // layer 2
    zero_f_k<<<4096, 256>>>(agg, N * HH / 4);
    scatter_k<<<2048, 256>>>(bufB, src, dst, agg, E);
    combine_k<<<cblk, 256, 131072>>>(agg, bufB, W1, b1, invn, bufA, N);

    // pooling + head
    pool_k<<<gblk, 256>>>(bufA, batch, gsum, cnt, N);
    final_k<<<B, 256>>>(gsum, cnt, Wo, bo, gamma, beta, (float*)d_out);
}

// round 3
// speedup vs baseline: 1.0939x; 1.0939x over previous
#include <cuda_runtime.h>
#include <math.h>

#define NN   200000
#define EE   600000
#define HH   128
#define OUTD 256
#define BMAXG 1024
#define BM   128
#define SCAN_B 512

// ---------------- scratch (device globals; no allocation) ----------------
__device__ float g_bufA[(size_t)NN * HH];   // 102.4 MB
__device__ float g_bufB[(size_t)NN * HH];   // 102.4 MB
__device__ float g_agg [(size_t)NN * HH];   // 102.4 MB
__device__ int   g_deg [NN];
__device__ int   g_cur [NN];
__device__ int   g_rowptr[NN + 1];
__device__ int   g_scanTmp[NN];
__device__ int   g_bsum[2048];
__device__ int   g_adj [2 * EE];            // 4.8 MB directed adjacency
__device__ float g_invn[NN];
__device__ float g_gsum[BMAXG * HH];
__device__ int   g_cnt [BMAXG];

// ---------------- helpers ----------------
__device__ __forceinline__ void redAdd4(float* p, float4 v) {
    asm volatile("red.global.add.v4.f32 [%0], {%1,%2,%3,%4};"
                 :: "l"(p), "f"(v.x), "f"(v.y), "f"(v.z), "f"(v.w) : "memory");
}

__device__ __forceinline__ float gelu_exact(float v) {
    return 0.5f * v * (1.0f + erff(v * 0.70710678118654752f));
}

__device__ __forceinline__ float4 f4add(float4 a, float4 b) {
    return make_float4(a.x + b.x, a.y + b.y, a.z + b.z, a.w + b.w);
}

// ---------------- zero kernels ----------------
__global__ void zero_f_k(float* p, int n4) {
    int i = blockIdx.x * blockDim.x + threadIdx.x;
    int s = gridDim.x * blockDim.x;
    float4 z = make_float4(0.f, 0.f, 0.f, 0.f);
    for (int f = i; f < n4; f += s) ((float4*)p)[f] = z;
}
__global__ void zero_i_k(int* p, int n) {
    int i = blockIdx.x * blockDim.x + threadIdx.x;
    int s = gridDim.x * blockDim.x;
    for (int f = i; f < n; f += s) p[f] = 0;
}

// ---------------- degree ----------------
__global__ void deg_k(const int* __restrict__ src, const int* __restrict__ dst,
                      int* __restrict__ deg, int E) {
    int e = blockIdx.x * blockDim.x + threadIdx.x;
    if (e < E) {
        atomicAdd(&deg[src[e]], 1);
        atomicAdd(&deg[dst[e]], 1);
    }
}

// ---------------- exclusive scan (3-kernel) ----------------
__global__ void scan1_k(const int* __restrict__ deg, int* __restrict__ tmp,
                        int* __restrict__ bsum, int n) {
    __shared__ int s[SCAN_B];
    int i = blockIdx.x * SCAN_B + threadIdx.x;
    int v = (i < n) ? deg[i] : 0;
    s[threadIdx.x] = v;
    __syncthreads();
    for (int o = 1; o < SCAN_B; o <<= 1) {
        int t = 0;
        if ((int)threadIdx.x >= o) t = s[threadIdx.x - o];
        __syncthreads();
        if ((int)threadIdx.x >= o) s[threadIdx.x] += t;
        __syncthreads();
    }
    if (i < n) tmp[i] = s[threadIdx.x];          // inclusive
    if (threadIdx.x == SCAN_B - 1) bsum[blockIdx.x] = s[SCAN_B - 1];
}
__global__ void scan2_k(int* __restrict__ bsum, int nb) {
    __shared__ int s[1024];
    int v = ((int)threadIdx.x < nb) ? bsum[threadIdx.x] : 0;
    s[threadIdx.x] = v;
    __syncthreads();
    for (int o = 1; o < 1024; o <<= 1) {
        int t = 0;
        if ((int)threadIdx.x >= o) t = s[threadIdx.x - o];
        __syncthreads();
        if ((int)threadIdx.x >= o) s[threadIdx.x] += t;
        __syncthreads();
    }
    if ((int)threadIdx.x < nb) bsum[threadIdx.x] = s[threadIdx.x];  // inclusive
}
__global__ void scan3_k(const int* __restrict__ deg, const int* __restrict__ tmp,
                        const int* __restrict__ bsum, int* __restrict__ rowptr,
                        int n, int Edir) {
    int i = blockIdx.x * SCAN_B + threadIdx.x;
    if (i < n) {
        int boff = (blockIdx.x > 0) ? bsum[blockIdx.x - 1] : 0;
        rowptr[i] = tmp[i] - deg[i] + boff;      // exclusive
    }
    if (i == 0) rowptr[n] = Edir;
}

// ---------------- CSR fill ----------------
__global__ void fill_k(const int* __restrict__ src, const int* __restrict__ dst,
                       const int* __restrict__ rowptr, int* __restrict__ cur,
                       int* __restrict__ adj, int E) {
    int e = blockIdx.x * blockDim.x + threadIdx.x;
    if (e < E) {
        int s = src[e], d = dst[e];
        int p = atomicAdd(&cur[d], 1);
        adj[rowptr[d] + p] = s;
        int q = atomicAdd(&cur[s], 1);
        adj[rowptr[s] + q] = d;
    }
}

// ---------------- embedding gather + invnorm ----------------
__global__ void gather_k(const int* __restrict__ x, const float* __restrict__ emb,
                         const int* __restrict__ deg, float* __restrict__ h,
                         float* __restrict__ invn, int n) {
    int gt = blockIdx.x * blockDim.x + threadIdx.x;
    int nd = gt >> 5, k4 = gt & 31;
    if (nd >= n) return;
    int t = x[nd];
    ((float4*)(h + (size_t)nd * HH))[k4] = ((const float4*)(emb + (size_t)t * HH))[k4];
    if (k4 == 0) invn[nd] = rsqrtf(fmaxf((float)deg[nd], 1.0f));
}

// ---------------- CSR pull-aggregation: agg[v] = invn[v] * sum_{u in N(v)} h[u] ----------------
__global__ void aggregate_k(const float* __restrict__ h, const int* __restrict__ rowptr,
                            const int* __restrict__ adj, const float* __restrict__ invn,
                            float* __restrict__ agg, int n) {
    int lane = threadIdx.x & 31;
    int v = (blockIdx.x * blockDim.x + threadIdx.x) >> 5;
    if (v >= n) return;
    int beg = rowptr[v], end = rowptr[v + 1];
    float4 a0 = make_float4(0.f, 0.f, 0.f, 0.f);
    float4 a1 = a0, a2 = a0, a3 = a0;
    int i = beg;
    for (; i + 4 <= end; i += 4) {
        int u0 = __ldg(adj + i);
        int u1 = __ldg(adj + i + 1);
        int u2 = __ldg(adj + i + 2);
        int u3 = __ldg(adj + i + 3);
        float4 v0 = __ldg(((const float4*)(h + (size_t)u0 * HH)) + lane);
        float4 v1 = __ldg(((const float4*)(h + (size_t)u1 * HH)) + lane);
        float4 v2 = __ldg(((const float4*)(h + (size_t)u2 * HH)) + lane);
        float4 v3 = __ldg(((const float4*)(h + (size_t)u3 * HH)) + lane);
        a0 = f4add(a0, v0);
        a1 = f4add(a1, v1);
        a2 = f4add(a2, v2);
        a3 = f4add(a3, v3);
    }
    for (; i < end; i++) {
        int u = __ldg(adj + i);
        a0 = f4add(a0, __ldg(((const float4*)(h + (size_t)u * HH)) + lane));
    }
    float4 s = f4add(f4add(a0, a1), f4add(a2, a3));
    float sc = invn[v];
    s.x *= sc; s.y *= sc; s.z *= sc; s.w *= sc;
    ((float4*)(agg + (size_t)v * HH))[lane] = s;
}

// ---------------- combine: out = gelu(agg @ W + b + hprev) (agg pre-scaled) ----------------
__global__ void combine_k(const float* __restrict__ agg, const float* __restrict__ hprev,
                          const float* __restrict__ W, const float* __restrict__ bias,
                          float* __restrict__ hout, int n) {
    extern __shared__ float smem[];
    float* As = smem;              // [128][128]
    float* Ws = smem + BM * HH;    // [128][128]
    int tid = threadIdx.x;
    int m0  = blockIdx.x * BM;

    for (int f = tid; f < HH * HH / 4; f += 256)
        ((float4*)Ws)[f] = ((const float4*)W)[f];

    for (int f = tid; f < BM * 32; f += 256) {
        int m = f >> 5, k4 = f & 31;
        int gm = m0 + m;
        float4 v = make_float4(0.f, 0.f, 0.f, 0.f);
        if (gm < n) v = ((const float4*)(agg + (size_t)gm * HH))[k4];
        ((float4*)(As + m * HH))[k4] = v;
    }
    __syncthreads();

    int tm = (tid >> 4) << 3;
    int tn = (tid & 15) << 3;

    float acc[8][8];
#pragma unroll
    for (int i = 0; i < 8; i++)
#pragma unroll
        for (int j = 0; j < 8; j++) acc[i][j] = 0.f;

#pragma unroll 1
    for (int kb = 0; kb < HH; kb += 4) {
        float4 a4[8];
#pragma unroll
        for (int i = 0; i < 8; i++)
            a4[i] = *(const float4*)(As + (tm + i) * HH + kb);
#pragma unroll
        for (int kk = 0; kk < 4; kk++) {
            float4 w0 = *(const float4*)(Ws + (kb + kk) * HH + tn);
            float4 w1 = *(const float4*)(Ws + (kb + kk) * HH + tn + 4);
#pragma unroll
            for (int i = 0; i < 8; i++) {
                float a = ((const float*)&a4[i])[kk];
                acc[i][0] = fmaf(a, w0.x, acc[i][0]);
                acc[i][1] = fmaf(a, w0.y, acc[i][1]);
                acc[i][2] = fmaf(a, w0.z, acc[i][2]);
                acc[i][3] = fmaf(a, w0.w, acc[i][3]);
                acc[i][4] = fmaf(a, w1.x, acc[i][4]);
                acc[i][5] = fmaf(a, w1.y, acc[i][5]);
                acc[i][6] = fmaf(a, w1.z, acc[i][6]);
                acc[i][7] = fmaf(a, w1.w, acc[i][7]);
            }
        }
    }

    float4 b0v = ((const float4*)bias)[tn >> 2];
    float4 b1v = ((const float4*)bias)[(tn >> 2) + 1];
#pragma unroll 1
    for (int i = 0; i < 8; i++) {
        int gm = m0 + tm + i;
        if (gm >= n) break;
        const float4* hp = (const float4*)(hprev + (size_t)gm * HH);
        float4 h0 = hp[tn >> 2];
        float4 h1 = hp[(tn >> 2) + 1];
        float4 o0, o1;
        o0.x = gelu_exact(acc[i][0] + b0v.x + h0.x);
        o0.y = gelu_exact(acc[i][1] + b0v.y + h0.y);
        o0.z = gelu_exact(acc[i][2] + b0v.z + h0.z);
        o0.w = gelu_exact(acc[i][3] + b0v.w + h0.w);
        o1.x = gelu_exact(acc[i][4] + b1v.x + h1.x);
        o1.y = gelu_exact(acc[i][5] + b1v.y + h1.y);
        o1.z = gelu_exact(acc[i][6] + b1v.z + h1.z);
        o1.w = gelu_exact(acc[i][7] + b1v.w + h1.w);
        float4* op = (float4*)(hout + (size_t)gm * HH);
        op[tn >> 2]       = o0;
        op[(tn >> 2) + 1] = o1;
    }
}

// ---------------- pooling ----------------
__global__ void pool_k(const float* __restrict__ h, const int* __restrict__ batch,
                       float* __restrict__ gsum, int* __restrict__ cnt, int n) {
    int gt = blockIdx.x * blockDim.x + threadIdx.x;
    int nd = gt >> 5, lane = gt & 31;
    if (nd >= n) return;
    int b = batch[nd];
    float4 v = ((const float4*)(h + (size_t)nd * HH))[lane];
    redAdd4(gsum + (size_t)b * HH + lane * 4, v);
    if (lane == 0) atomicAdd(&cnt[b], 1);
}

// ---------------- final head ----------------
__global__ void final_k(const float* __restrict__ gsum, const int* __restrict__ cnt,
                        const float* __restrict__ Wo, const float* __restrict__ bo,
                        const float* __restrict__ gamma, const float* __restrict__ beta,
                        float* __restrict__ out) {
    __shared__ float g[HH];
    __shared__ float rs[8], rq[8];
    int b = blockIdx.x, tid = threadIdx.x;
    if (tid < HH) g[tid] = gsum[(size_t)b * HH + tid] / fmaxf((float)cnt[b], 1.0f);
    __syncthreads();
    float acc = bo[tid];
#pragma unroll 4
    for (int k = 0; k < HH; k++) acc = fmaf(g[k], Wo[k * OUTD + tid], acc);
    float s = acc, q = acc * acc;
#pragma unroll
    for (int o = 16; o; o >>= 1) {
        s += __shfl_xor_sync(0xFFFFFFFFu, s, o);
        q += __shfl_xor_sync(0xFFFFFFFFu, q, o);
    }
    int w = tid >> 5;
    if ((tid & 31) == 0) { rs[w] = s; rq[w] = q; }
    __syncthreads();
    float ts = 0.f, tq = 0.f;
#pragma unroll
    for (int i = 0; i < 8; i++) { ts += rs[i]; tq += rq[i]; }
    float mu  = ts * (1.0f / OUTD);
    float var = tq * (1.0f / OUTD) - mu * mu;
    out[(size_t)b * OUTD + tid] = (acc - mu) * rsqrtf(var + 1e-5f) * gamma[tid] + beta[tid];
}

// ---------------- launch ----------------
extern "C" void kernel_launch(void* const* d_in, const int* in_sizes, int n_in,
                              void* d_out, int out_size) {
    const int* x     = (const int*)d_in[0];
    const int* ei    = (const int*)d_in[1];
    const int* batch = (const int*)d_in[2];
    int off = (n_in >= 13 && in_sizes[3] == 1) ? 4 : 3;
    const float* emb   = (const float*)d_in[off + 0];
    const float* W0    = (const float*)d_in[off + 1];
    const float* b0    = (const float*)d_in[off + 2];
    const float* W1    = (const float*)d_in[off + 3];
    const float* b1    = (const float*)d_in[off + 4];
    const float* Wo    = (const float*)d_in[off + 5];
    const float* bo    = (const float*)d_in[off + 6];
    const float* gamma = (const float*)d_in[off + 7];
    const float* beta  = (const float*)d_in[off + 8];

    int N = in_sizes[0];
    int E = in_sizes[1] / 2;
    int B = out_size / OUTD;

    float *bufA, *bufB, *agg, *invn, *gsum;
    int *deg, *cur, *rowptr, *scanTmp, *bsum, *adj, *cnt;
    cudaGetSymbolAddress((void**)&bufA, g_bufA);
    cudaGetSymbolAddress((void**)&bufB, g_bufB);
    cudaGetSymbolAddress((void**)&agg,  g_agg);
    cudaGetSymbolAddress((void**)&invn, g_invn);
    cudaGetSymbolAddress((void**)&gsum, g_gsum);
    cudaGetSymbolAddress((void**)&deg,  g_deg);
    cudaGetSymbolAddress((void**)&cur,  g_cur);
    cudaGetSymbolAddress((void**)&rowptr, g_rowptr);
    cudaGetSymbolAddress((void**)&scanTmp, g_scanTmp);
    cudaGetSymbolAddress((void**)&bsum, g_bsum);
    cudaGetSymbolAddress((void**)&adj,  g_adj);
    cudaGetSymbolAddress((void**)&cnt,  g_cnt);

    cudaFuncSetAttribute(combine_k, cudaFuncAttributeMaxDynamicSharedMemorySize, 131072);

    const int* src = ei;
    const int* dst = ei + E;

    int gthr = N * 32;
    int gblk = (gthr + 255) / 256;
    int cblk = (N + BM - 1) / BM;
    int nscan = (N + SCAN_B - 1) / SCAN_B;

    // degree + CSR build
    zero_i_k<<<256, 256>>>(deg, N);
    deg_k<<<(E + 255) / 256, 256>>>(src, dst, deg, E);
    scan1_k<<<nscan, SCAN_B>>>(deg, scanTmp, bsum, N);
    scan2_k<<<1, 1024>>>(bsum, nscan);
    scan3_k<<<nscan, SCAN_B>>>(deg, scanTmp, bsum, rowptr, N, 2 * E);
    zero_i_k<<<256, 256>>>(cur, N);
    fill_k<<<(E + 255) / 256, 256>>>(src, dst, rowptr, cur, adj, E);

    // embedding + invnorm
    gather_k<<<gblk, 256>>>(x, emb, deg, bufA, invn, N);

    // layer 1
    aggregate_k<<<(N * 32 + 255) / 256, 256>>>(bufA, rowptr, adj, invn, agg, N);
    combine_k<<<cblk, 256, 131072>>>(agg, bufA, W0, b0, bufB, N);

    // layer 2
    aggregate_k<<<(N * 32 + 255) / 256, 256>>>(bufB, rowptr, adj, invn, agg, N);
    combine_k<<<cblk, 256, 131072>>>(agg, bufB, W1, b1, bufA, N);

    // pooling + head
    zero_f_k<<<64, 256>>>(gsum, B * HH / 4);
    zero_i_k<<<1, 256>>>(cnt, B);
    pool_k<<<gblk, 256>>>(bufA, batch, gsum, cnt, N);
    final_k<<<B, 256>>>(gsum, cnt, Wo, bo, gamma, beta, (float*)d_out);
}

// round 4
// speedup vs baseline: 2.4337x; 2.2248x over previous
#include <cuda_runtime.h>
#include <math.h>
#include <stdint.h>

#define NN   200000
#define EE   600000
#define HH   128
#define OUTD 256
#define BMAXG 1024
#define BM   128
#define SCAN_B 512

// tf32 GEMM tile params
#define ASTRIDE 68     // 64-col chunk + 4 pad (conflict-free for A frag pattern)
#define WSTRIDE 136    // 128-col + 8 pad (conflict-free for B frag pattern)

// ---------------- scratch (device globals; no allocation) ----------------
__device__ float g_bufA[(size_t)NN * HH];
__device__ float g_bufB[(size_t)NN * HH];
__device__ float g_agg [(size_t)NN * HH];
__device__ int   g_deg [NN];
__device__ int   g_cur [NN];
__device__ int   g_rowptr[NN + 1];
__device__ int   g_scanTmp[NN];
__device__ int   g_bsum[2048];
__device__ int   g_adj [2 * EE];
__device__ float g_invn[NN];
__device__ float g_gsum[BMAXG * HH];
__device__ int   g_cnt [BMAXG];

// ---------------- helpers ----------------
__device__ __forceinline__ void redAdd4(float* p, float4 v) {
    asm volatile("red.global.add.v4.f32 [%0], {%1,%2,%3,%4};"
                 :: "l"(p), "f"(v.x), "f"(v.y), "f"(v.z), "f"(v.w) : "memory");
}
__device__ __forceinline__ float gelu_exact(float v) {
    return 0.5f * v * (1.0f + erff(v * 0.70710678118654752f));
}
__device__ __forceinline__ float4 f4add(float4 a, float4 b) {
    return make_float4(a.x + b.x, a.y + b.y, a.z + b.z, a.w + b.w);
}
__device__ __forceinline__ float tf32r(float x) {
    float y;
    asm("cvt.rna.tf32.f32 %0, %1;" : "=f"(y) : "f"(x));
    return y;
}
__device__ __forceinline__ void mma_tf32(float* c, const uint32_t* a, uint32_t b0, uint32_t b1) {
    asm volatile(
        "mma.sync.aligned.m16n8k8.row.col.f32.tf32.tf32.f32 "
        "{%0,%1,%2,%3}, {%4,%5,%6,%7}, {%8,%9}, {%0,%1,%2,%3};"
        : "+f"(c[0]), "+f"(c[1]), "+f"(c[2]), "+f"(c[3])
        : "r"(a[0]), "r"(a[1]), "r"(a[2]), "r"(a[3]), "r"(b0), "r"(b1));
}

// ---------------- zero kernels ----------------
__global__ void zero_f_k(float* p, int n4) {
    int i = blockIdx.x * blockDim.x + threadIdx.x;
    int s = gridDim.x * blockDim.x;
    float4 z = make_float4(0.f, 0.f, 0.f, 0.f);
    for (int f = i; f < n4; f += s) ((float4*)p)[f] = z;
}
__global__ void zero_i_k(int* p, int n) {
    int i = blockIdx.x * blockDim.x + threadIdx.x;
    int s = gridDim.x * blockDim.x;
    for (int f = i; f < n; f += s) p[f] = 0;
}

// ---------------- degree ----------------
__global__ void deg_k(const int* __restrict__ src, const int* __restrict__ dst,
                      int* __restrict__ deg, int E) {
    int e = blockIdx.x * blockDim.x + threadIdx.x;
    if (e < E) {
        atomicAdd(&deg[src[e]], 1);
        atomicAdd(&deg[dst[e]], 1);
    }
}

// ---------------- exclusive scan (3-kernel) ----------------
__global__ void scan1_k(const int* __restrict__ deg, int* __restrict__ tmp,
                        int* __restrict__ bsum, int n) {
    __shared__ int s[SCAN_B];
    int i = blockIdx.x * SCAN_B + threadIdx.x;
    int v = (i < n) ? deg[i] : 0;
    s[threadIdx.x] = v;
    __syncthreads();
    for (int o = 1; o < SCAN_B; o <<= 1) {
        int t = 0;
        if ((int)threadIdx.x >= o) t = s[threadIdx.x - o];
        __syncthreads();
        if ((int)threadIdx.x >= o) s[threadIdx.x] += t;
        __syncthreads();
    }
    if (i < n) tmp[i] = s[threadIdx.x];
    if (threadIdx.x == SCAN_B - 1) bsum[blockIdx.x] = s[SCAN_B - 1];
}
__global__ void scan2_k(int* __restrict__ bsum, int nb) {
    __shared__ int s[1024];
    int v = ((int)threadIdx.x < nb) ? bsum[threadIdx.x] : 0;
    s[threadIdx.x] = v;
    __syncthreads();
    for (int o = 1; o < 1024; o <<= 1) {
        int t = 0;
        if ((int)threadIdx.x >= o) t = s[threadIdx.x - o];
        __syncthreads();
        if ((int)threadIdx.x >= o) s[threadIdx.x] += t;
        __syncthreads();
    }
    if ((int)threadIdx.x < nb) bsum[threadIdx.x] = s[threadIdx.x];
}
__global__ void scan3_k(const int* __restrict__ deg, const int* __restrict__ tmp,
                        const int* __restrict__ bsum, int* __restrict__ rowptr,
                        int n, int Edir) {
    int i = blockIdx.x * SCAN_B + threadIdx.x;
    if (i < n) {
        int boff = (blockIdx.x > 0) ? bsum[blockIdx.x - 1] : 0;
        rowptr[i] = tmp[i] - deg[i] + boff;
    }
    if (i == 0) rowptr[n] = Edir;
}

// ---------------- CSR fill ----------------
__global__ void fill_k(const int* __restrict__ src, const int* __restrict__ dst,
                       const int* __restrict__ rowptr, int* __restrict__ cur,
                       int* __restrict__ adj, int E) {
    int e = blockIdx.x * blockDim.x + threadIdx.x;
    if (e < E) {
        int s = src[e], d = dst[e];
        int p = atomicAdd(&cur[d], 1);
        adj[rowptr[d] + p] = s;
        int q = atomicAdd(&cur[s], 1);
        adj[rowptr[s] + q] = d;
    }
}

// ---------------- embedding gather + invnorm ----------------
__global__ void gather_k(const int* __restrict__ x, const float* __restrict__ emb,
                         const int* __restrict__ deg, float* __restrict__ h,
                         float* __restrict__ invn, int n) {
    int gt = blockIdx.x * blockDim.x + threadIdx.x;
    int nd = gt >> 5, k4 = gt & 31;
    if (nd >= n) return;
    int t = x[nd];
    ((float4*)(h + (size_t)nd * HH))[k4] = ((const float4*)(emb + (size_t)t * HH))[k4];
    if (k4 == 0) invn[nd] = rsqrtf(fmaxf((float)deg[nd], 1.0f));
}

// ---------------- CSR pull-aggregation ----------------
__global__ void aggregate_k(const float* __restrict__ h, const int* __restrict__ rowptr,
                            const int* __restrict__ adj, const float* __restrict__ invn,
                            float* __restrict__ agg, int n) {
    int lane = threadIdx.x & 31;
    int v = (blockIdx.x * blockDim.x + threadIdx.x) >> 5;
    if (v >= n) return;
    int beg = rowptr[v], end = rowptr[v + 1];
    float4 a0 = make_float4(0.f, 0.f, 0.f, 0.f);
    float4 a1 = a0, a2 = a0, a3 = a0;
    int i = beg;
    for (; i + 4 <= end; i += 4) {
        int u0 = __ldg(adj + i);
        int u1 = __ldg(adj + i + 1);
        int u2 = __ldg(adj + i + 2);
        int u3 = __ldg(adj + i + 3);
        float4 v0 = __ldg(((const float4*)(h + (size_t)u0 * HH)) + lane);
        float4 v1 = __ldg(((const float4*)(h + (size_t)u1 * HH)) + lane);
        float4 v2 = __ldg(((const float4*)(h + (size_t)u2 * HH)) + lane);
        float4 v3 = __ldg(((const float4*)(h + (size_t)u3 * HH)) + lane);
        a0 = f4add(a0, v0);
        a1 = f4add(a1, v1);
        a2 = f4add(a2, v2);
        a3 = f4add(a3, v3);
    }
    for (; i < end; i++) {
        int u = __ldg(adj + i);
        a0 = f4add(a0, __ldg(((const float4*)(h + (size_t)u * HH)) + lane));
    }
    float4 s = f4add(f4add(a0, a1), f4add(a2, a3));
    float sc = invn[v];
    s.x *= sc; s.y *= sc; s.z *= sc; s.w *= sc;
    ((float4*)(agg + (size_t)v * HH))[lane] = s;
}

// ---------------- combine (TF32 tensor core): out = gelu(agg @ W + b + hprev) ----------------
// Block: 256 threads = 8 warps (4x2). Block tile 128x128, warp tile 32x64.
// K chunked by 64; A chunk [128][ASTRIDE], W chunk [64][WSTRIDE] in smem (tf32-rounded).
__global__ void combine_tc_k(const float* __restrict__ agg, const float* __restrict__ hprev,
                             const float* __restrict__ W, const float* __restrict__ bias,
                             float* __restrict__ hout, int n) {
    extern __shared__ float smem[];
    float* As = smem;                       // 128 * 68 = 8704 floats
    float* Ws = smem + 128 * ASTRIDE;       // 64 * 136 = 8704 floats
    int tid  = threadIdx.x;
    int lane = tid & 31;
    int warp = tid >> 5;
    int gid  = lane >> 2;    // 0..7
    int tig  = lane & 3;     // 0..3
    int wm   = warp >> 1;    // 0..3 -> M offset wm*32
    int wn   = warp & 1;     // 0..1 -> N offset wn*64
    int m0   = blockIdx.x * BM;
    int wm0  = wm * 32;
    int wn0  = wn * 64;

    float acc[2][8][4];
#pragma unroll
    for (int t = 0; t < 2; t++)
#pragma unroll
        for (int j = 0; j < 8; j++)
#pragma unroll
            for (int c = 0; c < 4; c++) acc[t][j][c] = 0.f;

#pragma unroll
    for (int kb = 0; kb < HH; kb += 64) {
        // ---- stage A chunk: rows m0..m0+127, cols kb..kb+63, tf32-rounded ----
        for (int f = tid; f < 128 * 16; f += 256) {
            int m = f >> 4, c4 = f & 15;
            int gm = m0 + m;
            float4 v = make_float4(0.f, 0.f, 0.f, 0.f);
            if (gm < n) v = __ldg((const float4*)(agg + (size_t)gm * HH + kb) + c4);
            v.x = tf32r(v.x); v.y = tf32r(v.y); v.z = tf32r(v.z); v.w = tf32r(v.w);
            *(float4*)(As + m * ASTRIDE + c4 * 4) = v;
        }
        // ---- stage W chunk: rows kb..kb+63 (k), cols 0..127 (n), tf32-rounded ----
        for (int f = tid; f < 64 * 32; f += 256) {
            int k = f >> 5, n4 = f & 31;
            float4 v = __ldg((const float4*)(W + (size_t)(kb + k) * HH) + n4);
            v.x = tf32r(v.x); v.y = tf32r(v.y); v.z = tf32r(v.z); v.w = tf32r(v.w);
            *(float4*)(Ws + k * WSTRIDE + n4 * 4) = v;
        }
        __syncthreads();

#pragma unroll
        for (int kk = 0; kk < 64; kk += 8) {
            // A fragments for 2 m16 tiles
            uint32_t afrag[2][4];
#pragma unroll
            for (int t = 0; t < 2; t++) {
                const float* ab = As + (wm0 + 16 * t + gid) * ASTRIDE + kk + tig;
                afrag[t][0] = __float_as_uint(ab[0]);
                afrag[t][1] = __float_as_uint(ab[8 * ASTRIDE]);
                afrag[t][2] = __float_as_uint(ab[4]);
                afrag[t][3] = __float_as_uint(ab[8 * ASTRIDE + 4]);
            }
#pragma unroll
            for (int j = 0; j < 8; j++) {
                const float* bb = Ws + (kk + tig) * WSTRIDE + wn0 + 8 * j + gid;
                uint32_t b0 = __float_as_uint(bb[0]);
                uint32_t b1 = __float_as_uint(bb[4 * WSTRIDE]);
                mma_tf32(acc[0][j], afrag[0], b0, b1);
                mma_tf32(acc[1][j], afrag[1], b0, b1);
            }
        }
        __syncthreads();
    }

    // ---- epilogue: bias + residual + exact GELU ----
#pragma unroll
    for (int j = 0; j < 8; j++) {
        int col = wn0 + 8 * j + 2 * tig;
        float2 bv = *(const float2*)(bias + col);
#pragma unroll
        for (int t = 0; t < 2; t++) {
            int r0 = m0 + wm0 + 16 * t + gid;
            if (r0 < n) {
                float2 hr = __ldg((const float2*)(hprev + (size_t)r0 * HH + col));
                float2 o;
                o.x = gelu_exact(acc[t][j][0] + bv.x + hr.x);
                o.y = gelu_exact(acc[t][j][1] + bv.y + hr.y);
                *(float2*)(hout + (size_t)r0 * HH + col) = o;
            }
            int r1 = r0 + 8;
            if (r1 < n) {
                float2 hr = __ldg((const float2*)(hprev + (size_t)r1 * HH + col));
                float2 o;
                o.x = gelu_exact(acc[t][j][2] + bv.x + hr.x);
                o.y = gelu_exact(acc[t][j][3] + bv.y + hr.y);
                *(float2*)(hout + (size_t)r1 * HH + col) = o;
            }
        }
    }
}

// ---------------- pooling ----------------
__global__ void pool_k(const float* __restrict__ h, const int* __restrict__ batch,
                       float* __restrict__ gsum, int* __restrict__ cnt, int n) {
    int gt = blockIdx.x * blockDim.x + threadIdx.x;
    int nd = gt >> 5, lane = gt & 31;
    if (nd >= n) return;
    int b = batch[nd];
    float4 v = ((const float4*)(h + (size_t)nd * HH))[lane];
    redAdd4(gsum + (size_t)b * HH + lane * 4, v);
    if (lane == 0) atomicAdd(&cnt[b], 1);
}

// ---------------- final head ----------------
__global__ void final_k(const float* __restrict__ gsum, const int* __restrict__ cnt,
                        const float* __restrict__ Wo, const float* __restrict__ bo,
                        const float* __restrict__ gamma, const float* __restrict__ beta,
                        float* __restrict__ out) {
    __shared__ float g[HH];
    __shared__ float rs[8], rq[8];
    int b = blockIdx.x, tid = threadIdx.x;
    if (tid < HH) g[tid] = gsum[(size_t)b * HH + tid] / fmaxf((float)cnt[b], 1.0f);
    __syncthreads();
    float acc = bo[tid];
#pragma unroll 4
    for (int k = 0; k < HH; k++) acc = fmaf(g[k], Wo[k * OUTD + tid], acc);
    float s = acc, q = acc * acc;
#pragma unroll
    for (int o = 16; o; o >>= 1) {
        s += __shfl_xor_sync(0xFFFFFFFFu, s, o);
        q += __shfl_xor_sync(0xFFFFFFFFu, q, o);
    }
    int w = tid >> 5;
    if ((tid & 31) == 0) { rs[w] = s; rq[w] = q; }
    __syncthreads();
    float ts = 0.f, tq = 0.f;
#pragma unroll
    for (int i = 0; i < 8; i++) { ts += rs[i]; tq += rq[i]; }
    float mu  = ts * (1.0f / OUTD);
    float var = tq * (1.0f / OUTD) - mu * mu;
    out[(size_t)b * OUTD + tid] = (acc - mu) * rsqrtf(var + 1e-5f) * gamma[tid] + beta[tid];
}

// ---------------- launch ----------------
extern "C" void kernel_launch(void* const* d_in, const int* in_sizes, int n_in,
                              void* d_out, int out_size) {
    const int* x     = (const int*)d_in[0];
    const int* ei    = (const int*)d_in[1];
    const int* batch = (const int*)d_in[2];
    int off = (n_in >= 13 && in_sizes[3] == 1) ? 4 : 3;
    const float* emb   = (const float*)d_in[off + 0];
    const float* W0    = (const float*)d_in[off + 1];
    const float* b0    = (const float*)d_in[off + 2];
    const float* W1    = (const float*)d_in[off + 3];
    const float* b1    = (const float*)d_in[off + 4];
    const float* Wo    = (const float*)d_in[off + 5];
    const float* bo    = (const float*)d_in[off + 6];
    const float* gamma = (const float*)d_in[off + 7];
    const float* beta  = (const float*)d_in[off + 8];

    int N = in_sizes[0];
    int E = in_sizes[1] / 2;
    int B = out_size / OUTD;

    float *bufA, *bufB, *agg, *invn, *gsum;
    int *deg, *cur, *rowptr, *scanTmp, *bsum, *adj, *cnt;
    cudaGetSymbolAddress((void**)&bufA, g_bufA);
    cudaGetSymbolAddress((void**)&bufB, g_bufB);
    cudaGetSymbolAddress((void**)&agg,  g_agg);
    cudaGetSymbolAddress((void**)&invn, g_invn);
    cudaGetSymbolAddress((void**)&gsum, g_gsum);
    cudaGetSymbolAddress((void**)&deg,  g_deg);
    cudaGetSymbolAddress((void**)&cur,  g_cur);
    cudaGetSymbolAddress((void**)&rowptr, g_rowptr);
    cudaGetSymbolAddress((void**)&scanTmp, g_scanTmp);
    cudaGetSymbolAddress((void**)&bsum, g_bsum);
    cudaGetSymbolAddress((void**)&adj,  g_adj);
    cudaGetSymbolAddress((void**)&cnt,  g_cnt);

    int smem_tc = (128 * ASTRIDE + 64 * WSTRIDE) * 4;   // 69632 bytes
    cudaFuncSetAttribute(combine_tc_k, cudaFuncAttributeMaxDynamicSharedMemorySize, smem_tc);

    const int* src = ei;
    const int* dst = ei + E;

    int gthr = N * 32;
    int gblk = (gthr + 255) / 256;
    int cblk = (N + BM - 1) / BM;
    int nscan = (N + SCAN_B - 1) / SCAN_B;

    // degree + CSR build
    zero_i_k<<<256, 256>>>(deg, N);
    deg_k<<<(E + 255) / 256, 256>>>(src, dst, deg, E);
    scan1_k<<<nscan, SCAN_B>>>(deg, scanTmp, bsum, N);
    scan2_k<<<1, 1024>>>(bsum, nscan);
    scan3_k<<<nscan, SCAN_B>>>(deg, scanTmp, bsum, rowptr, N, 2 * E);
    zero_i_k<<<256, 256>>>(cur, N);
    fill_k<<<(E + 255) / 256, 256>>>(src, dst, rowptr, cur, adj, E);

    // embedding + invnorm
    gather_k<<<gblk, 256>>>(x, emb, deg, bufA, invn, N);

    // layer 1
    aggregate_k<<<(N * 32 + 255) / 256, 256>>>(bufA, rowptr, adj, invn, agg, N);
    combine_tc_k<<<cblk, 256, smem_tc>>>(agg, bufA, W0, b0, bufB, N);

    // layer 2
    aggregate_k<<<(N * 32 + 255) / 256, 256>>>(bufB, rowptr, adj, invn, agg, N);
    combine_tc_k<<<cblk, 256, smem_tc>>>(agg, bufB, W1, b1, bufA, N);

    // pooling + head
    zero_f_k<<<64, 256>>>(gsum, B * HH / 4);
    zero_i_k<<<1, 256>>>(cnt, B);
    pool_k<<<gblk, 256>>>(bufA, batch, gsum, cnt, N);
    final_k<<<B, 256>>>(gsum, cnt, Wo, bo, gamma, beta, (float*)d_out);
}